// round 2
// baseline (speedup 1.0000x reference)
#include <cuda_runtime.h>

#define N_TOK 8192
#define DM    1024
#define DF    4096
#define NE    8

#define TM 64
#define TN 64
#define TK 16

// ---- scratch (static __device__, no allocations) ----
__device__ int   g_expert[N_TOK];
__device__ int   g_counts[NE];
__device__ int   g_offsets[NE + 1];
__device__ int   g_cursors[NE];
__device__ int   g_perm[N_TOK];
__device__ float g_h[(size_t)N_TOK * DF];   // grouped hidden activations

// ---- reset per launch (graph-replay safe) ----
__global__ void init_kernel() {
    int t = threadIdx.x;
    if (t < NE) { g_counts[t] = 0; g_cursors[t] = 0; }
}

// ---- gate: logits, argmax, one-hot output, per-expert counts ----
__global__ void gate_kernel(const float* __restrict__ x,
                            const float* __restrict__ gW,
                            const float* __restrict__ gb,
                            float* gate_out) {
    int tok  = (blockIdx.x * blockDim.x + threadIdx.x) >> 5;
    int lane = threadIdx.x & 31;
    if (tok >= N_TOK) return;
    const float* xr = x + (size_t)tok * DM;
    float acc[NE];
#pragma unroll
    for (int e = 0; e < NE; e++) acc[e] = 0.f;
    for (int k = lane; k < DM; k += 32) {
        float xv = xr[k];
        const float* w = gW + k * NE;
#pragma unroll
        for (int e = 0; e < NE; e++) acc[e] += xv * w[e];
    }
#pragma unroll
    for (int e = 0; e < NE; e++) {
#pragma unroll
        for (int o = 16; o; o >>= 1) acc[e] += __shfl_xor_sync(0xffffffffu, acc[e], o);
        acc[e] += gb[e];
    }
    int best = 0;
#pragma unroll
    for (int e = 1; e < NE; e++) if (acc[e] > acc[best]) best = e;  // first-max wins
    if (lane == 0) {
        g_expert[tok] = best;
        atomicAdd(&g_counts[best], 1);
    }
    if (gate_out && lane < NE)
        gate_out[(size_t)tok * NE + lane] = (lane == best) ? 1.0f : 0.0f;
}

__global__ void scan_kernel() {
    int s = 0;
    for (int e = 0; e < NE; e++) { g_offsets[e] = s; s += g_counts[e]; }
    g_offsets[NE] = s;
}

__global__ void scatter_kernel() {
    int t = blockIdx.x * blockDim.x + threadIdx.x;
    if (t >= N_TOK) return;
    int e = g_expert[t];
    int pos = g_offsets[e] + atomicAdd(&g_cursors[e], 1);
    g_perm[pos] = t;
}

// ---- up projection: h = relu(x[perm] @ up_W[e] + up_b[e]), grouped rows ----
__global__ void __launch_bounds__(256, 4)
up_kernel(const float* __restrict__ x,
          const float* __restrict__ upW,
          const float* __restrict__ upb) {
    int e   = blockIdx.z;
    int off = g_offsets[e];
    int cnt = g_offsets[e + 1] - off;
    int m0  = blockIdx.y * TM;
    if (m0 >= cnt) return;
    int n0  = blockIdx.x * TN;
    const float* W = upW + (size_t)e * DM * DF;

    __shared__ float As[TK][TM];
    __shared__ float Bs[TK][TN];

    int tid = threadIdx.x;
    int lm = tid >> 2;           // 0..63 : A row within tile
    int lk = (tid & 3) * 4;      // 0,4,8,12 : A k-segment
    int bk = tid >> 4;           // 0..15 : B k row
    int bn = (tid & 15) * 4;     // B n-segment
    int ty = tid >> 4, tx = tid & 15;

    int mrow = m0 + lm;
    int arow = g_perm[off + ((mrow < cnt) ? mrow : 0)];   // dup-safe gather
    const float* aptr = x + (size_t)arow * DM + lk;

    float acc[4][4];
#pragma unroll
    for (int i = 0; i < 4; i++)
#pragma unroll
        for (int j = 0; j < 4; j++) acc[i][j] = 0.f;

    for (int k0 = 0; k0 < DM; k0 += TK) {
        float4 av = *(const float4*)(aptr + k0);
        float4 bv = *(const float4*)(W + (size_t)(k0 + bk) * DF + n0 + bn);
        As[lk + 0][lm] = av.x; As[lk + 1][lm] = av.y;
        As[lk + 2][lm] = av.z; As[lk + 3][lm] = av.w;
        *(float4*)&Bs[bk][bn] = bv;
        __syncthreads();
#pragma unroll
        for (int kk = 0; kk < TK; kk++) {
            float4 a4 = *(const float4*)&As[kk][ty * 4];
            float4 b4 = *(const float4*)&Bs[kk][tx * 4];
            float aa[4] = {a4.x, a4.y, a4.z, a4.w};
            float bb[4] = {b4.x, b4.y, b4.z, b4.w};
#pragma unroll
            for (int i = 0; i < 4; i++)
#pragma unroll
                for (int j = 0; j < 4; j++) acc[i][j] += aa[i] * bb[j];
        }
        __syncthreads();
    }

    const float* bvec = upb + (size_t)e * DF + n0;
#pragma unroll
    for (int i = 0; i < 4; i++) {
        int mg = m0 + ty * 4 + i;
        if (mg >= cnt) break;
        float* hrow = g_h + (size_t)(off + mg) * DF + n0;
#pragma unroll
        for (int j = 0; j < 4; j++) {
            float v = acc[i][j] + bvec[tx * 4 + j];
            hrow[tx * 4 + j] = v > 0.f ? v : 0.f;
        }
    }
}

// ---- down projection: out[perm] = h @ down_W[e] + down_b[e] ----
__global__ void __launch_bounds__(256, 4)
down_kernel(const float* __restrict__ dW,
            const float* __restrict__ db,
            float* __restrict__ out) {
    int e   = blockIdx.z;
    int off = g_offsets[e];
    int cnt = g_offsets[e + 1] - off;
    int m0  = blockIdx.y * TM;
    if (m0 >= cnt) return;
    int n0  = blockIdx.x * TN;
    const float* W = dW + (size_t)e * DF * DM;

    __shared__ float As[TK][TM];
    __shared__ float Bs[TK][TN];

    int tid = threadIdx.x;
    int lm = tid >> 2;
    int lk = (tid & 3) * 4;
    int bk = tid >> 4;
    int bn = (tid & 15) * 4;
    int ty = tid >> 4, tx = tid & 15;

    int mrow = m0 + lm;
    int agrow = off + ((mrow < cnt) ? mrow : 0);
    const float* aptr = g_h + (size_t)agrow * DF + lk;

    float acc[4][4];
#pragma unroll
    for (int i = 0; i < 4; i++)
#pragma unroll
        for (int j = 0; j < 4; j++) acc[i][j] = 0.f;

    for (int k0 = 0; k0 < DF; k0 += TK) {
        float4 av = *(const float4*)(aptr + k0);
        float4 bv = *(const float4*)(W + (size_t)(k0 + bk) * DM + n0 + bn);
        As[lk + 0][lm] = av.x; As[lk + 1][lm] = av.y;
        As[lk + 2][lm] = av.z; As[lk + 3][lm] = av.w;
        *(float4*)&Bs[bk][bn] = bv;
        __syncthreads();
#pragma unroll
        for (int kk = 0; kk < TK; kk++) {
            float4 a4 = *(const float4*)&As[kk][ty * 4];
            float4 b4 = *(const float4*)&Bs[kk][tx * 4];
            float aa[4] = {a4.x, a4.y, a4.z, a4.w};
            float bb[4] = {b4.x, b4.y, b4.z, b4.w};
#pragma unroll
            for (int i = 0; i < 4; i++)
#pragma unroll
                for (int j = 0; j < 4; j++) acc[i][j] += aa[i] * bb[j];
        }
        __syncthreads();
    }

    const float* bvec = db + (size_t)e * DM + n0;
#pragma unroll
    for (int i = 0; i < 4; i++) {
        int mg = m0 + ty * 4 + i;
        if (mg >= cnt) break;
        int row = g_perm[off + mg];
        float* orow = out + (size_t)row * DM + n0;
#pragma unroll
        for (int j = 0; j < 4; j++)
            orow[tx * 4 + j] = acc[i][j] + bvec[tx * 4 + j];
    }
}

extern "C" void kernel_launch(void* const* d_in, const int* in_sizes, int n_in,
                              void* d_out, int out_size) {
    const float* x   = (const float*)d_in[0];
    const float* gW  = (const float*)d_in[1];
    const float* gb  = (const float*)d_in[2];
    const float* upW = (const float*)d_in[3];
    const float* upb = (const float*)d_in[4];
    const float* dW  = (const float*)d_in[5];
    const float* db  = (const float*)d_in[6];
    float* out = (float*)d_out;

    // gate one-hot lives after the main output if the harness concatenates the tuple
    float* gate_out = nullptr;
    if (out_size >= N_TOK * DM + N_TOK * NE)
        gate_out = out + (size_t)out_size - (size_t)N_TOK * NE;

    init_kernel<<<1, 32>>>();
    gate_kernel<<<N_TOK / 8, 256>>>(x, gW, gb, gate_out);
    scan_kernel<<<1, 1>>>();
    scatter_kernel<<<N_TOK / 256, 256>>>();
    up_kernel<<<dim3(DF / TN, N_TOK / TM, NE), 256>>>(x, upW, upb);
    down_kernel<<<dim3(DM / TN, N_TOK / TM, NE), 256>>>(dW, db, out);
}

// round 4
// speedup vs baseline: 3.9517x; 3.9517x over previous
#include <cuda_runtime.h>
#include <cuda_bf16.h>
#include <cstdint>

#define N_TOK 8192
#define DM    1024
#define DF    4096
#define NE    8
#define MAX_TILES 71   // worst case: 64 + 7 partial tiles

// ---------------- scratch (static device, no allocations) ----------------
__device__ int   g_expert[N_TOK];
__device__ int   g_counts[NE];
__device__ int   g_offsets[NE + 1];
__device__ int   g_cursors[NE];
__device__ int   g_perm[N_TOK];
__device__ int   g_tile_prefix[NE + 1];

__device__ __nv_bfloat16 g_xh[(size_t)N_TOK * DM];
__device__ __nv_bfloat16 g_xl[(size_t)N_TOK * DM];
__device__ __nv_bfloat16 g_uwh[(size_t)NE * DF * DM];   // up W^T  [e][n=DF][k=DM]
__device__ __nv_bfloat16 g_uwl[(size_t)NE * DF * DM];
__device__ __nv_bfloat16 g_dwh[(size_t)NE * DM * DF];   // down W^T [e][n=DM][k=DF]
__device__ __nv_bfloat16 g_dwl[(size_t)NE * DM * DF];
__device__ __nv_bfloat16 g_hh[(size_t)N_TOK * DF];
__device__ __nv_bfloat16 g_hl[(size_t)N_TOK * DF];

// ---------------- PTX helpers (baseline ISA only — no sm_103a features) ----------------
__device__ __forceinline__ uint32_t smem_u32(const void* p) {
    uint32_t a;
    asm("{ .reg .u64 t; cvta.to.shared.u64 t, %1; cvt.u32.u64 %0, t; }" : "=r"(a) : "l"(p));
    return a;
}
__device__ __forceinline__ void cp_async16(uint32_t dst, const void* src) {
    asm volatile("cp.async.cg.shared.global [%0], [%1], 16;"
                 :: "r"(dst), "l"(__cvta_generic_to_global(src)));
}
__device__ __forceinline__ void cp_commit() {
    asm volatile("cp.async.commit_group;");
}
template <int N>
__device__ __forceinline__ void cp_wait() {
    asm volatile("cp.async.wait_group %0;" :: "n"(N));
}
#define LDSM4(r0, r1, r2, r3, addr)                                            \
    asm volatile("ldmatrix.sync.aligned.m8n8.x4.shared.b16 {%0,%1,%2,%3}, [%4];" \
                 : "=r"(r0), "=r"(r1), "=r"(r2), "=r"(r3) : "r"(addr))
#define LDSM2(r0, r1, addr)                                                    \
    asm volatile("ldmatrix.sync.aligned.m8n8.x2.shared.b16 {%0,%1}, [%2];"     \
                 : "=r"(r0), "=r"(r1) : "r"(addr))
#define MMA16816(c, a0, a1, a2, a3, b0, b1)                                    \
    asm volatile("mma.sync.aligned.m16n8k16.row.col.f32.bf16.bf16.f32 "        \
                 "{%0,%1,%2,%3},{%4,%5,%6,%7},{%8,%9},{%0,%1,%2,%3};"          \
                 : "+f"((c)[0]), "+f"((c)[1]), "+f"((c)[2]), "+f"((c)[3])      \
                 : "r"(a0), "r"(a1), "r"(a2), "r"(a3), "r"(b0), "r"(b1))

__device__ __forceinline__ void split_f32(float v, __nv_bfloat16& h, __nv_bfloat16& l) {
    h = __float2bfloat16(v);
    l = __float2bfloat16(v - __bfloat162float(h));
}

// ---------------- routing kernels ----------------
__global__ void init_kernel() {
    int t = threadIdx.x;
    if (t < NE) { g_counts[t] = 0; g_cursors[t] = 0; }
}

__global__ void gate_kernel(const float* __restrict__ x,
                            const float* __restrict__ gW,
                            const float* __restrict__ gb,
                            float* gate_out) {
    int tok  = (blockIdx.x * blockDim.x + threadIdx.x) >> 5;
    int lane = threadIdx.x & 31;
    if (tok >= N_TOK) return;
    const float* xr = x + (size_t)tok * DM;
    float acc[NE];
#pragma unroll
    for (int e = 0; e < NE; e++) acc[e] = 0.f;
    for (int k = lane; k < DM; k += 32) {
        float xv = xr[k];
        const float* w = gW + k * NE;
#pragma unroll
        for (int e = 0; e < NE; e++) acc[e] += xv * w[e];
    }
#pragma unroll
    for (int e = 0; e < NE; e++) {
#pragma unroll
        for (int o = 16; o; o >>= 1) acc[e] += __shfl_xor_sync(0xffffffffu, acc[e], o);
        acc[e] += gb[e];
    }
    int best = 0;
#pragma unroll
    for (int e = 1; e < NE; e++) if (acc[e] > acc[best]) best = e;
    if (lane == 0) {
        g_expert[tok] = best;
        atomicAdd(&g_counts[best], 1);
    }
    if (gate_out && lane < NE)
        gate_out[(size_t)tok * NE + lane] = (lane == best) ? 1.0f : 0.0f;
}

__global__ void scan_kernel() {
    int s = 0, tp = 0;
    for (int e = 0; e < NE; e++) {
        g_offsets[e] = s;
        g_tile_prefix[e] = tp;
        tp += (g_counts[e] + 127) >> 7;
        s += g_counts[e];
    }
    g_offsets[NE] = s;
    g_tile_prefix[NE] = tp;
}

__global__ void scatter_kernel() {
    int t = blockIdx.x * blockDim.x + threadIdx.x;
    if (t >= N_TOK) return;
    int e = g_expert[t];
    int pos = g_offsets[e] + atomicAdd(&g_cursors[e], 1);
    g_perm[pos] = t;
}

// ---------------- conversions ----------------
__global__ void conv_x_kernel(const float* __restrict__ x) {
    int p = blockIdx.x;
    int t = threadIdx.x;
    int tok = g_perm[p];
    float4 v = ((const float4*)(x + (size_t)tok * DM))[t];
    __nv_bfloat16 h0, h1, h2, h3, l0, l1, l2, l3;
    split_f32(v.x, h0, l0); split_f32(v.y, h1, l1);
    split_f32(v.z, h2, l2); split_f32(v.w, h3, l3);
    __nv_bfloat162* dh = (__nv_bfloat162*)(g_xh + (size_t)p * DM);
    __nv_bfloat162* dl = (__nv_bfloat162*)(g_xl + (size_t)p * DM);
    dh[2 * t]     = __nv_bfloat162(h0, h1);
    dh[2 * t + 1] = __nv_bfloat162(h2, h3);
    dl[2 * t]     = __nv_bfloat162(l0, l1);
    dl[2 * t + 1] = __nv_bfloat162(l2, l3);
}

// W: [e][K][N] fp32  ->  T: [e][N][K] bf16 hi/lo
template <bool UP>
__global__ void conv_w_kernel(const float* __restrict__ W, int K, int N) {
    __shared__ float tile[32][33];
    __nv_bfloat16* Th = UP ? g_uwh : g_dwh;
    __nv_bfloat16* Tl = UP ? g_uwl : g_dwl;
    int e  = blockIdx.z;
    int n0 = blockIdx.x * 32;
    int k0 = blockIdx.y * 32;
    int tx = threadIdx.x, ty = threadIdx.y;
    const float* Wp = W + (size_t)e * K * N;
#pragma unroll
    for (int i = 0; i < 4; i++)
        tile[ty + i * 8][tx] = Wp[(size_t)(k0 + ty + i * 8) * N + n0 + tx];
    __syncthreads();
    size_t base = (size_t)e * N * K;
#pragma unroll
    for (int i = 0; i < 4; i++) {
        float v = tile[tx][ty + i * 8];
        __nv_bfloat16 h, l;
        split_f32(v, h, l);
        size_t idx = base + (size_t)(n0 + ty + i * 8) * K + k0 + tx;
        Th[idx] = h;
        Tl[idx] = l;
    }
}

// ---------------- HMMA grouped GEMM ----------------
// CTA tile 128(M) x 128(N) x 32(K).  8 warps: warp_m in {0,1} (x64), warp_n in {0..3} (x32).
// SMEM per stage: 4 tiles (Ah, Al, Bh, Bl), each 128 rows x 80B (64B data + 16B pad). 3 stages.
#define ROW_B   80
#define TILE_B  (128 * ROW_B)     // 10240
#define STAGE_B (4 * TILE_B)      // 40960
#define NSTAGE  3
#define SMEM_BYTES (NSTAGE * STAGE_B)

template <bool IS_UP>
__global__ void __launch_bounds__(256, 1)
gemm_kernel(const float* __restrict__ bias, float* __restrict__ out) {
    constexpr int K   = IS_UP ? DM : DF;
    constexpr int NT  = IS_UP ? DF : DM;
    constexpr int NCH = K / 32;

    int ty = blockIdx.y;
    if (ty >= g_tile_prefix[NE]) return;
    int e = 0;
    while (ty >= g_tile_prefix[e + 1]) e++;
    int off = g_offsets[e];
    int cnt = g_offsets[e + 1] - off;
    int m0  = (ty - g_tile_prefix[e]) * 128;
    int n0  = blockIdx.x * 128;
    int valid = cnt - m0; if (valid > 128) valid = 128;

    extern __shared__ char smem[];
    uint32_t sb = smem_u32(smem);

    int tid = threadIdx.x, lane = tid & 31, wid = tid >> 5;
    int wm = (wid & 1) * 64, wn = (wid >> 1) * 32;
    int g = lane >> 2, t4 = lane & 3;

    const __nv_bfloat16* Ah = (IS_UP ? g_xh  : g_hh)  + (size_t)(off + m0) * K;
    const __nv_bfloat16* Al = (IS_UP ? g_xl  : g_hl)  + (size_t)(off + m0) * K;
    const __nv_bfloat16* Bh = (IS_UP ? g_uwh : g_dwh) + ((size_t)e * NT + n0) * K;
    const __nv_bfloat16* Bl = (IS_UP ? g_uwl : g_dwl) + ((size_t)e * NT + n0) * K;

    float acc[4][4][4];
#pragma unroll
    for (int i = 0; i < 4; i++)
#pragma unroll
        for (int j = 0; j < 4; j++)
#pragma unroll
            for (int r = 0; r < 4; r++) acc[i][j][r] = 0.f;

    // loader: 2048 x 16B chunks per stage, 8 per thread; tile = i>>1 (compile-time per unroll)
    auto load_chunk = [&](int c, int st) {
#pragma unroll
        for (int i = 0; i < 8; i++) {
            int idx  = tid + i * 256;
            int tile = i >> 1;                 // 0=Ah 1=Al 2=Bh 3=Bl
            int row  = (idx >> 2) & 127;
            int seg  = idx & 3;
            int r = row;
            if (tile < 2 && r >= valid) r = 0;     // dup-safe clamp for A
            const __nv_bfloat16* base =
                (tile == 0) ? Ah : (tile == 1) ? Al : (tile == 2) ? Bh : Bl;
            const __nv_bfloat16* src = base + (size_t)r * K + c * 32 + seg * 8;
            uint32_t dst = sb + st * STAGE_B + tile * TILE_B + row * ROW_B + seg * 16;
            cp_async16(dst, src);
        }
    };

    load_chunk(0, 0); cp_commit();
    load_chunk(1, 1); cp_commit();

    for (int c = 0; c < NCH; c++) {
        int st = c % NSTAGE;
        cp_wait<1>();
        __syncthreads();
        if (c + 2 < NCH) load_chunk(c + 2, (c + 2) % NSTAGE);
        cp_commit();   // empty groups at tail keep FIFO aligned

        uint32_t stb = sb + st * STAGE_B;
#pragma unroll
        for (int kk = 0; kk < 2; kk++) {
            uint32_t ah[4][4], al[4][4], bh[4][2], bl[4][2];
#pragma unroll
            for (int mi = 0; mi < 4; mi++) {
                uint32_t rb = (uint32_t)(wm + mi * 16 + (lane & 15)) * ROW_B
                            + kk * 32 + ((lane >> 4) & 1) * 16;
                LDSM4(ah[mi][0], ah[mi][1], ah[mi][2], ah[mi][3], stb + 0 * TILE_B + rb);
                LDSM4(al[mi][0], al[mi][1], al[mi][2], al[mi][3], stb + 1 * TILE_B + rb);
            }
#pragma unroll
            for (int ni = 0; ni < 4; ni++) {
                uint32_t rb = (uint32_t)(wn + ni * 8 + (lane & 7)) * ROW_B
                            + kk * 32 + ((lane >> 3) & 1) * 16;
                LDSM2(bh[ni][0], bh[ni][1], stb + 2 * TILE_B + rb);
                LDSM2(bl[ni][0], bl[ni][1], stb + 3 * TILE_B + rb);
            }
#pragma unroll
            for (int mi = 0; mi < 4; mi++)
#pragma unroll
                for (int ni = 0; ni < 4; ni++)
                    MMA16816(acc[mi][ni], ah[mi][0], ah[mi][1], ah[mi][2], ah[mi][3],
                             bh[ni][0], bh[ni][1]);
#pragma unroll
            for (int mi = 0; mi < 4; mi++)
#pragma unroll
                for (int ni = 0; ni < 4; ni++)
                    MMA16816(acc[mi][ni], al[mi][0], al[mi][1], al[mi][2], al[mi][3],
                             bh[ni][0], bh[ni][1]);
#pragma unroll
            for (int mi = 0; mi < 4; mi++)
#pragma unroll
                for (int ni = 0; ni < 4; ni++)
                    MMA16816(acc[mi][ni], ah[mi][0], ah[mi][1], ah[mi][2], ah[mi][3],
                             bl[ni][0], bl[ni][1]);
        }
    }

    // ---------------- epilogue (direct global stores) ----------------
    const float* bptr = bias + (size_t)e * NT + n0;
#pragma unroll
    for (int mi = 0; mi < 4; mi++) {
#pragma unroll
        for (int rr = 0; rr < 2; rr++) {
            int m = wm + mi * 16 + g + rr * 8;
            if (m >= valid) continue;
            if (IS_UP) {
                size_t pos = (size_t)(off + m0 + m);
                __nv_bfloat16* hrow = g_hh + pos * DF + n0;
                __nv_bfloat16* lrow = g_hl + pos * DF + n0;
#pragma unroll
                for (int ni = 0; ni < 4; ni++) {
                    int bn = wn + ni * 8 + 2 * t4;
                    float v0 = acc[mi][ni][rr * 2 + 0] + bptr[bn];
                    float v1 = acc[mi][ni][rr * 2 + 1] + bptr[bn + 1];
                    v0 = v0 > 0.f ? v0 : 0.f;
                    v1 = v1 > 0.f ? v1 : 0.f;
                    __nv_bfloat16 h0, l0, h1, l1;
                    split_f32(v0, h0, l0);
                    split_f32(v1, h1, l1);
                    *(__nv_bfloat162*)(hrow + bn) = __nv_bfloat162(h0, h1);
                    *(__nv_bfloat162*)(lrow + bn) = __nv_bfloat162(l0, l1);
                }
            } else {
                int tok = g_perm[off + m0 + m];
                float* orow = out + (size_t)tok * DM + n0;
#pragma unroll
                for (int ni = 0; ni < 4; ni++) {
                    int bn = wn + ni * 8 + 2 * t4;
                    float2 v;
                    v.x = acc[mi][ni][rr * 2 + 0] + bptr[bn];
                    v.y = acc[mi][ni][rr * 2 + 1] + bptr[bn + 1];
                    *(float2*)(orow + bn) = v;
                }
            }
        }
    }
}

// ---------------- launch ----------------
extern "C" void kernel_launch(void* const* d_in, const int* in_sizes, int n_in,
                              void* d_out, int out_size) {
    const float* x   = (const float*)d_in[0];
    const float* gW  = (const float*)d_in[1];
    const float* gb  = (const float*)d_in[2];
    const float* upW = (const float*)d_in[3];
    const float* upb = (const float*)d_in[4];
    const float* dW  = (const float*)d_in[5];
    const float* db  = (const float*)d_in[6];
    float* out = (float*)d_out;

    float* gate_out = nullptr;
    if (out_size >= N_TOK * DM + N_TOK * NE)
        gate_out = out + (size_t)out_size - (size_t)N_TOK * NE;

    cudaFuncSetAttribute(gemm_kernel<true>,  cudaFuncAttributeMaxDynamicSharedMemorySize, SMEM_BYTES);
    cudaFuncSetAttribute(gemm_kernel<false>, cudaFuncAttributeMaxDynamicSharedMemorySize, SMEM_BYTES);

    init_kernel<<<1, 32>>>();
    gate_kernel<<<N_TOK / 8, 256>>>(x, gW, gb, gate_out);
    scan_kernel<<<1, 1>>>();
    scatter_kernel<<<N_TOK / 256, 256>>>();
    conv_x_kernel<<<N_TOK, 256>>>(x);

    dim3 b32(32, 8);
    conv_w_kernel<true><<<dim3(DF / 32, DM / 32, NE), b32>>>(upW, DM, DF);
    conv_w_kernel<false><<<dim3(DM / 32, DF / 32, NE), b32>>>(dW, DF, DM);

    gemm_kernel<true><<<dim3(DF / 128, MAX_TILES), 256, SMEM_BYTES>>>(upb, nullptr);
    gemm_kernel<false><<<dim3(DM / 128, MAX_TILES), 256, SMEM_BYTES>>>(db, out);
}

// round 5
// speedup vs baseline: 5.0772x; 1.2848x over previous
#include <cuda_runtime.h>
#include <cuda_bf16.h>
#include <cstdint>

#define N_TOK 8192
#define DM    1024
#define DF    4096
#define NE    8
#define MAX_TILES 71   // worst case: 64 + 7 partial tiles (128-row tiles)

// ---------------- scratch (static device, no allocations) ----------------
__device__ int   g_expert[N_TOK];
__device__ int   g_counts[NE];
__device__ int   g_offsets[NE + 1];
__device__ int   g_cursors[NE];
__device__ int   g_perm[N_TOK];
__device__ int   g_tile_prefix[NE + 1];

__device__ __nv_bfloat16 g_xh[(size_t)N_TOK * DM];
__device__ __nv_bfloat16 g_xl[(size_t)N_TOK * DM];
__device__ __nv_bfloat16 g_uwh[(size_t)NE * DF * DM];   // up W^T  [e][n=DF][k=DM]
__device__ __nv_bfloat16 g_uwl[(size_t)NE * DF * DM];
__device__ __nv_bfloat16 g_dwh[(size_t)NE * DM * DF];   // down W^T [e][n=DM][k=DF]
__device__ __nv_bfloat16 g_dwl[(size_t)NE * DM * DF];
__device__ __nv_bfloat16 g_hh[(size_t)N_TOK * DF];
__device__ __nv_bfloat16 g_hl[(size_t)N_TOK * DF];

// ---------------- PTX helpers (baseline ISA only) ----------------
__device__ __forceinline__ uint32_t smem_u32(const void* p) {
    uint32_t a;
    asm("{ .reg .u64 t; cvta.to.shared.u64 t, %1; cvt.u32.u64 %0, t; }" : "=r"(a) : "l"(p));
    return a;
}
__device__ __forceinline__ void cp_async16(uint32_t dst, const void* src) {
    asm volatile("cp.async.cg.shared.global [%0], [%1], 16;"
                 :: "r"(dst), "l"(__cvta_generic_to_global(src)));
}
__device__ __forceinline__ void cp_commit() {
    asm volatile("cp.async.commit_group;");
}
template <int N>
__device__ __forceinline__ void cp_wait() {
    asm volatile("cp.async.wait_group %0;" :: "n"(N));
}
#define LDSM4(r0, r1, r2, r3, addr)                                            \
    asm volatile("ldmatrix.sync.aligned.m8n8.x4.shared.b16 {%0,%1,%2,%3}, [%4];" \
                 : "=r"(r0), "=r"(r1), "=r"(r2), "=r"(r3) : "r"(addr))
#define MMA16816(c, a0, a1, a2, a3, b0, b1)                                    \
    asm volatile("mma.sync.aligned.m16n8k16.row.col.f32.bf16.bf16.f32 "        \
                 "{%0,%1,%2,%3},{%4,%5,%6,%7},{%8,%9},{%0,%1,%2,%3};"          \
                 : "+f"((c)[0]), "+f"((c)[1]), "+f"((c)[2]), "+f"((c)[3])      \
                 : "r"(a0), "r"(a1), "r"(a2), "r"(a3), "r"(b0), "r"(b1))

__device__ __forceinline__ void split_f32(float v, __nv_bfloat16& h, __nv_bfloat16& l) {
    h = __float2bfloat16(v);
    l = __float2bfloat16(v - __bfloat162float(h));
}

// ---------------- routing kernels ----------------
__global__ void init_kernel() {
    int t = threadIdx.x;
    if (t < NE) { g_counts[t] = 0; g_cursors[t] = 0; }
}

__global__ void gate_kernel(const float* __restrict__ x,
                            const float* __restrict__ gW,
                            const float* __restrict__ gb,
                            float* gate_out) {
    int tok  = (blockIdx.x * blockDim.x + threadIdx.x) >> 5;
    int lane = threadIdx.x & 31;
    if (tok >= N_TOK) return;
    const float* xr = x + (size_t)tok * DM;
    float acc[NE];
#pragma unroll
    for (int e = 0; e < NE; e++) acc[e] = 0.f;
    for (int k = lane; k < DM; k += 32) {
        float xv = xr[k];
        const float* w = gW + k * NE;
#pragma unroll
        for (int e = 0; e < NE; e++) acc[e] += xv * w[e];
    }
#pragma unroll
    for (int e = 0; e < NE; e++) {
#pragma unroll
        for (int o = 16; o; o >>= 1) acc[e] += __shfl_xor_sync(0xffffffffu, acc[e], o);
        acc[e] += gb[e];
    }
    int best = 0;
#pragma unroll
    for (int e = 1; e < NE; e++) if (acc[e] > acc[best]) best = e;
    if (lane == 0) {
        g_expert[tok] = best;
        atomicAdd(&g_counts[best], 1);
    }
    if (gate_out && lane < NE)
        gate_out[(size_t)tok * NE + lane] = (lane == best) ? 1.0f : 0.0f;
}

__global__ void scan_kernel() {
    int s = 0, tp = 0;
    for (int e = 0; e < NE; e++) {
        g_offsets[e] = s;
        g_tile_prefix[e] = tp;
        tp += (g_counts[e] + 127) >> 7;
        s += g_counts[e];
    }
    g_offsets[NE] = s;
    g_tile_prefix[NE] = tp;
}

__global__ void scatter_kernel() {
    int t = blockIdx.x * blockDim.x + threadIdx.x;
    if (t >= N_TOK) return;
    int e = g_expert[t];
    int pos = g_offsets[e] + atomicAdd(&g_cursors[e], 1);
    g_perm[pos] = t;
}

// ---------------- conversions ----------------
__global__ void conv_x_kernel(const float* __restrict__ x) {
    int p = blockIdx.x;
    int t = threadIdx.x;
    int tok = g_perm[p];
    float4 v = ((const float4*)(x + (size_t)tok * DM))[t];
    __nv_bfloat16 h0, h1, h2, h3, l0, l1, l2, l3;
    split_f32(v.x, h0, l0); split_f32(v.y, h1, l1);
    split_f32(v.z, h2, l2); split_f32(v.w, h3, l3);
    __nv_bfloat162* dh = (__nv_bfloat162*)(g_xh + (size_t)p * DM);
    __nv_bfloat162* dl = (__nv_bfloat162*)(g_xl + (size_t)p * DM);
    dh[2 * t]     = __nv_bfloat162(h0, h1);
    dh[2 * t + 1] = __nv_bfloat162(h2, h3);
    dl[2 * t]     = __nv_bfloat162(l0, l1);
    dl[2 * t + 1] = __nv_bfloat162(l2, l3);
}

// W: [e][K][N] fp32  ->  T: [e][N][K] bf16 hi/lo
template <bool UP>
__global__ void conv_w_kernel(const float* __restrict__ W, int K, int N) {
    __shared__ float tile[32][33];
    __nv_bfloat16* Th = UP ? g_uwh : g_dwh;
    __nv_bfloat16* Tl = UP ? g_uwl : g_dwl;
    int e  = blockIdx.z;
    int n0 = blockIdx.x * 32;
    int k0 = blockIdx.y * 32;
    int tx = threadIdx.x, ty = threadIdx.y;
    const float* Wp = W + (size_t)e * K * N;
#pragma unroll
    for (int i = 0; i < 4; i++)
        tile[ty + i * 8][tx] = Wp[(size_t)(k0 + ty + i * 8) * N + n0 + tx];
    __syncthreads();
    size_t base = (size_t)e * N * K;
#pragma unroll
    for (int i = 0; i < 4; i++) {
        float v = tile[tx][ty + i * 8];
        __nv_bfloat16 h, l;
        split_f32(v, h, l);
        size_t idx = base + (size_t)(n0 + ty + i * 8) * K + k0 + tx;
        Th[idx] = h;
        Tl[idx] = l;
    }
}

// ---------------- HMMA grouped GEMM ----------------
// CTA tile 128(M) x 256(N) x 64(K). 512 threads, 16 warps as (4m x 4n), warp tile 32x64.
// SMEM stage: Ah(128), Al(128), Bh(256), Bl(256) rows x 144B (128B data + 16B pad).
// 2-stage double buffer: 2 x 110592 = 221184 bytes.
#define ROW_B    144
#define OFF_AH   0
#define OFF_AL   (128 * ROW_B)            // 18432
#define OFF_BH   (256 * ROW_B)            // 36864
#define OFF_BL   (OFF_BH + 256 * ROW_B)   // 73728
#define STAGE_B  (OFF_BL + 256 * ROW_B)   // 110592
#define SMEM_BYTES (2 * STAGE_B)

template <bool IS_UP>
__global__ void __launch_bounds__(512, 1)
gemm_kernel(const float* __restrict__ bias, float* __restrict__ out) {
    constexpr int K   = IS_UP ? DM : DF;
    constexpr int NT  = IS_UP ? DF : DM;
    constexpr int NCH = K / 64;

    int ty = blockIdx.y;
    if (ty >= g_tile_prefix[NE]) return;
    int e = 0;
    while (ty >= g_tile_prefix[e + 1]) e++;
    int off = g_offsets[e];
    int cnt = g_offsets[e + 1] - off;
    int m0  = (ty - g_tile_prefix[e]) * 128;
    int n0  = blockIdx.x * 256;
    int valid = cnt - m0; if (valid > 128) valid = 128;

    extern __shared__ char smem[];
    uint32_t sb = smem_u32(smem);

    int tid = threadIdx.x, lane = tid & 31, wid = tid >> 5;
    int wm = (wid & 3) * 32;        // 0,32,64,96
    int wn = (wid >> 2) * 64;       // 0,64,128,192
    int g = lane >> 2, t4 = lane & 3;

    const __nv_bfloat16* Ah = (IS_UP ? g_xh  : g_hh)  + (size_t)(off + m0) * K;
    const __nv_bfloat16* Al = (IS_UP ? g_xl  : g_hl)  + (size_t)(off + m0) * K;
    const __nv_bfloat16* Bh = (IS_UP ? g_uwh : g_dwh) + ((size_t)e * NT + n0) * K;
    const __nv_bfloat16* Bl = (IS_UP ? g_uwl : g_dwl) + ((size_t)e * NT + n0) * K;

    float acc[2][8][4];
#pragma unroll
    for (int i = 0; i < 2; i++)
#pragma unroll
        for (int j = 0; j < 8; j++)
#pragma unroll
            for (int r = 0; r < 4; r++) acc[i][j][r] = 0.f;

    // loader: 6144 16B-chunks per stage, 12 per thread; i -> tile compile-time
    // i 0-1: Ah, 2-3: Al, 4-7: Bh, 8-11: Bl
    auto load_chunk = [&](int c, int st) {
        int rbase = tid >> 3;          // 0..63
        int seg   = tid & 7;
        uint32_t dstb = sb + st * STAGE_B + seg * 16;
        int col = c * 64 + seg * 8;
#pragma unroll
        for (int i = 0; i < 12; i++) {
            int tile = (i < 2) ? 0 : (i < 4) ? 1 : (i < 8) ? 2 : 3;
            int row  = rbase + ((i < 4) ? (i & 1) : (i & 3)) * 64;
            int r = row;
            if (tile < 2 && r >= valid) r = 0;   // dup-safe A clamp
            const __nv_bfloat16* base =
                (tile == 0) ? Ah : (tile == 1) ? Al : (tile == 2) ? Bh : Bl;
            uint32_t toff = (tile == 0) ? OFF_AH : (tile == 1) ? OFF_AL
                          : (tile == 2) ? OFF_BH : OFF_BL;
            cp_async16(dstb + toff + (uint32_t)row * ROW_B,
                       base + (size_t)r * K + col);
        }
    };

    load_chunk(0, 0);
    cp_commit();

    for (int c = 0; c < NCH; c++) {
        cp_wait<0>();
        __syncthreads();
        if (c + 1 < NCH) { load_chunk(c + 1, (c + 1) & 1); cp_commit(); }

        uint32_t stb = sb + (c & 1) * STAGE_B;
#pragma unroll
        for (int kk = 0; kk < 4; kk++) {
            uint32_t kb = kk * 32;
            // A hi
            uint32_t ah[2][4];
#pragma unroll
            for (int mi = 0; mi < 2; mi++) {
                uint32_t rb = stb + OFF_AH
                            + (uint32_t)(wm + mi * 16 + (lane & 15)) * ROW_B
                            + kb + ((lane >> 4) & 1) * 16;
                LDSM4(ah[mi][0], ah[mi][1], ah[mi][2], ah[mi][3], rb);
            }
            // B hi (x4: two n-octets per op)
            uint32_t bh[8][2];
#pragma unroll
            for (int p = 0; p < 4; p++) {
                uint32_t rb = stb + OFF_BH
                            + (uint32_t)(wn + p * 16 + ((lane >> 4) & 1) * 8 + (lane & 7)) * ROW_B
                            + kb + ((lane >> 3) & 1) * 16;
                LDSM4(bh[2 * p][0], bh[2 * p][1], bh[2 * p + 1][0], bh[2 * p + 1][1], rb);
            }
            // P1 = Ah * Bh
#pragma unroll
            for (int mi = 0; mi < 2; mi++)
#pragma unroll
                for (int ni = 0; ni < 8; ni++)
                    MMA16816(acc[mi][ni], ah[mi][0], ah[mi][1], ah[mi][2], ah[mi][3],
                             bh[ni][0], bh[ni][1]);
            // A lo, P2 = Al * Bh
            {
                uint32_t al[2][4];
#pragma unroll
                for (int mi = 0; mi < 2; mi++) {
                    uint32_t rb = stb + OFF_AL
                                + (uint32_t)(wm + mi * 16 + (lane & 15)) * ROW_B
                                + kb + ((lane >> 4) & 1) * 16;
                    LDSM4(al[mi][0], al[mi][1], al[mi][2], al[mi][3], rb);
                }
#pragma unroll
                for (int mi = 0; mi < 2; mi++)
#pragma unroll
                    for (int ni = 0; ni < 8; ni++)
                        MMA16816(acc[mi][ni], al[mi][0], al[mi][1], al[mi][2], al[mi][3],
                                 bh[ni][0], bh[ni][1]);
            }
            // B lo, P3 = Ah * Bl (reuses bh storage)
#pragma unroll
            for (int p = 0; p < 4; p++) {
                uint32_t rb = stb + OFF_BL
                            + (uint32_t)(wn + p * 16 + ((lane >> 4) & 1) * 8 + (lane & 7)) * ROW_B
                            + kb + ((lane >> 3) & 1) * 16;
                LDSM4(bh[2 * p][0], bh[2 * p][1], bh[2 * p + 1][0], bh[2 * p + 1][1], rb);
            }
#pragma unroll
            for (int mi = 0; mi < 2; mi++)
#pragma unroll
                for (int ni = 0; ni < 8; ni++)
                    MMA16816(acc[mi][ni], ah[mi][0], ah[mi][1], ah[mi][2], ah[mi][3],
                             bh[ni][0], bh[ni][1]);
        }
    }

    // ---------------- epilogue (direct global stores) ----------------
    const float* bptr = bias + (size_t)e * NT + n0;
#pragma unroll
    for (int mi = 0; mi < 2; mi++) {
#pragma unroll
        for (int rr = 0; rr < 2; rr++) {
            int m = wm + mi * 16 + g + rr * 8;
            if (m >= valid) continue;
            if (IS_UP) {
                size_t pos = (size_t)(off + m0 + m);
                __nv_bfloat16* hrow = g_hh + pos * DF + n0;
                __nv_bfloat16* lrow = g_hl + pos * DF + n0;
#pragma unroll
                for (int ni = 0; ni < 8; ni++) {
                    int bn = wn + ni * 8 + 2 * t4;
                    float v0 = acc[mi][ni][rr * 2 + 0] + bptr[bn];
                    float v1 = acc[mi][ni][rr * 2 + 1] + bptr[bn + 1];
                    v0 = v0 > 0.f ? v0 : 0.f;
                    v1 = v1 > 0.f ? v1 : 0.f;
                    __nv_bfloat16 h0, l0, h1, l1;
                    split_f32(v0, h0, l0);
                    split_f32(v1, h1, l1);
                    *(__nv_bfloat162*)(hrow + bn) = __nv_bfloat162(h0, h1);
                    *(__nv_bfloat162*)(lrow + bn) = __nv_bfloat162(l0, l1);
                }
            } else {
                int tok = g_perm[off + m0 + m];
                float* orow = out + (size_t)tok * DM + n0;
#pragma unroll
                for (int ni = 0; ni < 8; ni++) {
                    int bn = wn + ni * 8 + 2 * t4;
                    float2 v;
                    v.x = acc[mi][ni][rr * 2 + 0] + bptr[bn];
                    v.y = acc[mi][ni][rr * 2 + 1] + bptr[bn + 1];
                    *(float2*)(orow + bn) = v;
                }
            }
        }
    }
}

// ---------------- launch ----------------
extern "C" void kernel_launch(void* const* d_in, const int* in_sizes, int n_in,
                              void* d_out, int out_size) {
    const float* x   = (const float*)d_in[0];
    const float* gW  = (const float*)d_in[1];
    const float* gb  = (const float*)d_in[2];
    const float* upW = (const float*)d_in[3];
    const float* upb = (const float*)d_in[4];
    const float* dW  = (const float*)d_in[5];
    const float* db  = (const float*)d_in[6];
    float* out = (float*)d_out;

    float* gate_out = nullptr;
    if (out_size >= N_TOK * DM + N_TOK * NE)
        gate_out = out + (size_t)out_size - (size_t)N_TOK * NE;

    cudaFuncSetAttribute(gemm_kernel<true>,  cudaFuncAttributeMaxDynamicSharedMemorySize, SMEM_BYTES);
    cudaFuncSetAttribute(gemm_kernel<false>, cudaFuncAttributeMaxDynamicSharedMemorySize, SMEM_BYTES);

    init_kernel<<<1, 32>>>();
    gate_kernel<<<N_TOK / 8, 256>>>(x, gW, gb, gate_out);
    scan_kernel<<<1, 1>>>();
    scatter_kernel<<<N_TOK / 256, 256>>>();
    conv_x_kernel<<<N_TOK, 256>>>(x);

    dim3 b32(32, 8);
    conv_w_kernel<true><<<dim3(DF / 32, DM / 32, NE), b32>>>(upW, DM, DF);
    conv_w_kernel<false><<<dim3(DM / 32, DF / 32, NE), b32>>>(dW, DF, DM);

    gemm_kernel<true><<<dim3(DF / 256, MAX_TILES), 512, SMEM_BYTES>>>(upb, nullptr);
    gemm_kernel<false><<<dim3(DM / 256, MAX_TILES), 512, SMEM_BYTES>>>(db, out);
}